// round 10
// baseline (speedup 1.0000x reference)
#include <cuda_runtime.h>
#include <cuda_bf16.h>
#include <cstdint>

#define BATCH 16
#define SEQ   2048
#define DIM   512
typedef __nv_bfloat16 bf;

// ---------------------------------------------------------------------------
// Persistent scratch (device globals — allocation-free per harness rules)
// ---------------------------------------------------------------------------
__device__ bf    g_qinh[(size_t)BATCH * SEQ * DIM];   // query hi
__device__ bf    g_qinl[(size_t)BATCH * SEQ * DIM];   // query lo
__device__ bf    g_Winh[DIM * DIM];
__device__ bf    g_Winl[DIM * DIM];
__device__ bf    g_Wouth[DIM * 2 * DIM];
__device__ bf    g_Woutl[DIM * 2 * DIM];
__device__ bf    g_qh  [(size_t)BATCH * SEQ * DIM];   // q hi/lo
__device__ bf    g_ql  [(size_t)BATCH * SEQ * DIM];
__device__ bf    g_qTh [(size_t)BATCH * DIM * SEQ];   // q^T hi/lo
__device__ bf    g_qTl [(size_t)BATCH * DIM * SEQ];
__device__ bf    g_Wh  [(size_t)BATCH * SEQ * SEQ];   // softmax weights hi/lo
__device__ bf    g_Wl  [(size_t)BATCH * SEQ * SEQ];
__device__ bf    g_mixh[(size_t)BATCH * SEQ * DIM];
__device__ bf    g_mixl[(size_t)BATCH * SEQ * DIM];
__device__ float g_S   [(size_t)BATCH * SEQ * SEQ];   // fp32 scores

// ---------------------------------------------------------------------------
// PTX helpers (portable: ldmatrix / mma.sync / cp.async)
// ---------------------------------------------------------------------------
__device__ __forceinline__ uint32_t smem_u32(const void* p) {
    uint32_t a;
    asm("{ .reg .u64 t; cvta.to.shared.u64 t, %1; cvt.u32.u64 %0, t; }" : "=r"(a) : "l"(p));
    return a;
}
__device__ __forceinline__ void ldsm4(uint32_t* r, uint32_t addr) {
    asm volatile("ldmatrix.sync.aligned.m8n8.x4.shared.b16 {%0,%1,%2,%3}, [%4];"
                 : "=r"(r[0]), "=r"(r[1]), "=r"(r[2]), "=r"(r[3]) : "r"(addr));
}
__device__ __forceinline__ void mma16816(float* c, const uint32_t* a, const uint32_t* b) {
    asm volatile(
        "mma.sync.aligned.m16n8k16.row.col.f32.bf16.bf16.f32 "
        "{%0,%1,%2,%3}, {%4,%5,%6,%7}, {%8,%9}, {%0,%1,%2,%3};"
        : "+f"(c[0]), "+f"(c[1]), "+f"(c[2]), "+f"(c[3])
        : "r"(a[0]), "r"(a[1]), "r"(a[2]), "r"(a[3]), "r"(b[0]), "r"(b[1]));
}
#define CP16(s, g)  asm volatile("cp.async.cg.shared.global [%0], [%1], 16;" :: "r"(s), "l"(g) : "memory")
#define CP_COMMIT() asm volatile("cp.async.commit_group;" ::: "memory")
#define CP_WAIT0()  asm volatile("cp.async.wait_group 0;" ::: "memory")

__device__ __forceinline__ void split1(float v, bf& h, bf& l) {
    h = __float2bfloat16_rn(v);
    l = __float2bfloat16_rn(v - __bfloat162float(h));
}

// ---------------------------------------------------------------------------
// GEMM: C[128(M) x 256(N)] = A @ B^T, bf16 hi/lo, 3-term split, fp32 accum.
// Operands K-major bf16. K = nk*32. CONCAT: chunks>=16 read A1 (lda 512).
// EPI: 0 -> fp32 C, 1 -> bf16 hi/lo (Ch, Cl).
// 256 threads = 8 warps (2m x 4n), warp tile 64x64, mma m16n8k16.
// 2-stage cp.async pipeline, one __syncthreads per chunk. 1 CTA/SM.
// ---------------------------------------------------------------------------
#define LDS 40  // bf16 per smem row (80B; 16B-aligned segments, conflict-free ldmatrix)
#define A_BYTES (128 * LDS * 2)          // 10240 per half
#define B_BYTES (256 * LDS * 2)          // 20480 per half
#define STG_BYTES (2 * A_BYTES + 2 * B_BYTES)  // 61440

template<int CONCAT, int EPI>
__device__ __forceinline__ void gemm_bf(
    const bf* __restrict__ Ah, const bf* __restrict__ Al,
    const bf* __restrict__ A1h, const bf* __restrict__ A1l, long lda,
    const bf* __restrict__ Bh, const bf* __restrict__ Bl, long ldb,
    int nk,
    float* __restrict__ C, bf* __restrict__ Ch, bf* __restrict__ Cl, long ldc,
    int m0, int n0)
{
    extern __shared__ bf sm[];
    const uint32_t uS = smem_u32(sm);

    const int tid = threadIdx.x;
    const int wid = tid >> 5, lane = tid & 31;
    const int wm = wid >> 2, wn = wid & 3;            // 2m x 4n
    const int ra = tid >> 1, h16 = (tid & 1) << 4;    // A loader: row, 16-col half

    const uint32_t aoffA = ((uint32_t)ra * LDS + h16) * 2;
    const uint32_t aoffB = ((uint32_t)tid * LDS) * 2;

    auto issue = [&](int kc, int st) {
        const bf* a_h;
        const bf* a_l;
        if (CONCAT && kc >= 16) {
            a_h = A1h + (size_t)(m0 + ra) * 512 + (size_t)(kc - 16) * 32 + h16;
            a_l = A1l + (size_t)(m0 + ra) * 512 + (size_t)(kc - 16) * 32 + h16;
        } else {
            a_h = Ah + (size_t)(m0 + ra) * lda + (size_t)kc * 32 + h16;
            a_l = Al + (size_t)(m0 + ra) * lda + (size_t)kc * 32 + h16;
        }
        const uint32_t base = uS + (uint32_t)st * STG_BYTES;
        // A: 128 rows, 2 threads/row
        CP16(base + aoffA,                a_h);
        CP16(base + aoffA + 16,           a_h + 8);
        CP16(base + A_BYTES + aoffA,      a_l);
        CP16(base + A_BYTES + aoffA + 16, a_l + 8);
        // B: 256 rows, 1 thread/row, 32 cols
        const bf* b_h = Bh + (size_t)(n0 + tid) * ldb + (size_t)kc * 32;
        const bf* b_l = Bl + (size_t)(n0 + tid) * ldb + (size_t)kc * 32;
        const uint32_t bb = base + 2 * A_BYTES + aoffB;
#pragma unroll
        for (int i = 0; i < 4; ++i) {
            CP16(bb + i * 16,           b_h + i * 8);
            CP16(bb + B_BYTES + i * 16, b_l + i * 8);
        }
    };

    float acc[4][8][4] = {};

    issue(0, 0);
    CP_COMMIT();

    for (int kc = 0; kc < nk; ++kc) {
        const int st = kc & 1;
        CP_WAIT0();
        __syncthreads();
        if (kc + 1 < nk) { issue(kc + 1, st ^ 1); CP_COMMIT(); }

        const uint32_t sA  = uS + (uint32_t)st * STG_BYTES;
        const uint32_t sAl_ = sA + A_BYTES;
        const uint32_t sB  = sA + 2 * A_BYTES;
        const uint32_t sBl_ = sB + B_BYTES;

#pragma unroll
        for (int kk = 0; kk < 2; ++kk) {
            // A fragments: 4 x m16 (64 rows), hi + lo
            uint32_t ah[4][4], al[4][4];
#pragma unroll
            for (int im = 0; im < 4; ++im) {
                const uint32_t ao =
                    ((uint32_t)(wm * 64 + im * 16 + (lane & 15)) * LDS
                     + kk * 16 + ((lane & 16) ? 8 : 0)) * 2;
                ldsm4(ah[im], sA + ao);
                ldsm4(al[im], sAl_ + ao);
            }
            const uint32_t boff =
                ((uint32_t)(wn * 64 + (lane & 7) + ((lane & 16) ? 8 : 0)) * LDS
                 + kk * 16 + ((lane & 8) ? 8 : 0)) * 2;
#pragma unroll
            for (int jj = 0; jj < 4; ++jj) {
                uint32_t tb[4], tl[4];
                ldsm4(tb, sB + boff + jj * 16 * LDS * 2);
                ldsm4(tl, sBl_ + boff + jj * 16 * LDS * 2);
#pragma unroll
                for (int half = 0; half < 2; ++half) {
                    const int j = 2 * jj + half;
                    uint32_t bh2[2] = {tb[2 * half], tb[2 * half + 1]};
                    uint32_t bl2[2] = {tl[2 * half], tl[2 * half + 1]};
#pragma unroll
                    for (int im = 0; im < 4; ++im) {
                        mma16816(acc[im][j], ah[im], bh2);
                        mma16816(acc[im][j], ah[im], bl2);
                        mma16816(acc[im][j], al[im], bh2);
                    }
                }
            }
        }
    }

    // epilogue
    const int g = lane >> 2, tg = lane & 3;
#pragma unroll
    for (int im = 0; im < 4; ++im) {
        const size_t row = (size_t)(m0 + wm * 64 + im * 16 + g);
#pragma unroll
        for (int j = 0; j < 8; ++j) {
            const size_t col = (size_t)(n0 + wn * 64 + j * 8 + tg * 2);
            if (EPI == 0) {
                *(float2*)(C + row * ldc + col)       = make_float2(acc[im][j][0], acc[im][j][1]);
                *(float2*)(C + (row + 8) * ldc + col) = make_float2(acc[im][j][2], acc[im][j][3]);
            } else {
                bf h0, l0, h1, l1;
#pragma unroll
                for (int p = 0; p < 2; ++p) {
                    const size_t rr = (row + p * 8) * ldc + col;
                    split1(acc[im][j][2 * p],     h0, l0);
                    split1(acc[im][j][2 * p + 1], h1, l1);
                    *(uint32_t*)(Ch + rr) = ((uint32_t)__bfloat16_as_ushort(h1) << 16) | __bfloat16_as_ushort(h0);
                    *(uint32_t*)(Cl + rr) = ((uint32_t)__bfloat16_as_ushort(l1) << 16) | __bfloat16_as_ushort(l0);
                }
            }
        }
    }
}

// ---------------------------------------------------------------------------
// GEMM kernels
// ---------------------------------------------------------------------------
__global__ void __launch_bounds__(256, 1) k_qproj() {
    gemm_bf<0, 1>(g_qinh, g_qinl, nullptr, nullptr, DIM,
                  g_Winh, g_Winl, DIM, 16,
                  nullptr, g_qh, g_ql, DIM, blockIdx.y * 128, blockIdx.x * 256);
}
__global__ void __launch_bounds__(256, 1) k_scores() {
    const int m0 = blockIdx.y * 128, n0 = blockIdx.x * 256;
    if (n0 > m0 + 127) return;   // fully masked causal tile
    const size_t qo = (size_t)blockIdx.z * SEQ * DIM;
    gemm_bf<0, 0>(g_qh + qo, g_ql + qo, nullptr, nullptr, DIM,
                  g_qh + qo, g_ql + qo, DIM, 16,
                  g_S + (size_t)blockIdx.z * SEQ * SEQ, nullptr, nullptr, SEQ,
                  m0, n0);
}
__global__ void __launch_bounds__(256, 1) k_mix() {
    const int b = blockIdx.z, m0 = blockIdx.y * 128, n0 = blockIdx.x * 256;
    const size_t wo = (size_t)b * SEQ * SEQ, qo = (size_t)b * DIM * SEQ;
    const size_t mo = (size_t)b * SEQ * DIM;
    gemm_bf<0, 1>(g_Wh + wo, g_Wl + wo, nullptr, nullptr, SEQ,
                  g_qTh + qo, g_qTl + qo, SEQ, m0 / 32 + 4,
                  nullptr, g_mixh + mo, g_mixl + mo, DIM, m0, n0);
}
__global__ void __launch_bounds__(256, 1) k_out(float* __restrict__ out) {
    gemm_bf<1, 0>(g_mixh, g_mixl, g_qh, g_ql, DIM,
                  g_Wouth, g_Woutl, 2 * DIM, 32,
                  out, nullptr, nullptr, DIM, blockIdx.y * 128, blockIdx.x * 256);
}

// ---------------------------------------------------------------------------
// fp32 -> bf16 hi/lo split (pre-convert inputs)
// ---------------------------------------------------------------------------
__global__ void __launch_bounds__(256) k_cvt(const float* __restrict__ src,
                                             bf* __restrict__ dh, bf* __restrict__ dl,
                                             size_t n) {
    size_t i = ((size_t)blockIdx.x * 256 + threadIdx.x) * 4;
    if (i >= n) return;
    float4 v = *(const float4*)(src + i);
    bf h0, l0, h1, l1, h2, l2, h3, l3;
    split1(v.x, h0, l0); split1(v.y, h1, l1);
    split1(v.z, h2, l2); split1(v.w, h3, l3);
    *(uint2*)(dh + i) = make_uint2(
        ((uint32_t)__bfloat16_as_ushort(h1) << 16) | __bfloat16_as_ushort(h0),
        ((uint32_t)__bfloat16_as_ushort(h3) << 16) | __bfloat16_as_ushort(h2));
    *(uint2*)(dl + i) = make_uint2(
        ((uint32_t)__bfloat16_as_ushort(l1) << 16) | __bfloat16_as_ushort(l0),
        ((uint32_t)__bfloat16_as_ushort(l3) << 16) | __bfloat16_as_ushort(l2));
}

// ---------------------------------------------------------------------------
// Transpose bf16 hi/lo: qT[b][d][n] = q[b][n][d]
// ---------------------------------------------------------------------------
__global__ void __launch_bounds__(256) k_transpose() {
    __shared__ bf th[32][33];
    __shared__ bf tl[32][33];
    const int b = blockIdx.z, n0 = blockIdx.x * 32, d0 = blockIdx.y * 32;
    const int tx = threadIdx.x & 31, ty = threadIdx.x >> 5;
    const size_t so = (size_t)b * SEQ * DIM, to = (size_t)b * DIM * SEQ;
#pragma unroll
    for (int j = 0; j < 4; ++j) {
        const size_t idx = so + (size_t)(n0 + ty + 8 * j) * DIM + d0 + tx;
        th[ty + 8 * j][tx] = g_qh[idx];
        tl[ty + 8 * j][tx] = g_ql[idx];
    }
    __syncthreads();
#pragma unroll
    for (int j = 0; j < 4; ++j) {
        const size_t idx = to + (size_t)(d0 + ty + 8 * j) * SEQ + n0 + tx;
        g_qTh[idx] = th[tx][ty + 8 * j];
        g_qTl[idx] = tl[tx][ty + 8 * j];
    }
}

// ---------------------------------------------------------------------------
// Softmax: row n over keys m < n (strict causal); emits bf16 hi/lo weights.
// Only writes up to the 128-aligned limit that k_mix actually reads.
// ---------------------------------------------------------------------------
__global__ void __launch_bounds__(256) k_softmax() {
    const int n = blockIdx.x, b = blockIdx.y;
    const size_t ro = ((size_t)b * SEQ + n) * SEQ;
    const float* row = g_S + ro;
    bf* wh = g_Wh + ro;
    bf* wl = g_Wl + ro;
    const int tid = threadIdx.x;
    const int lim = (n / 128) * 128 + 128;   // k_mix never reads beyond this
    const bf z = __float2bfloat16_rn(0.f);
    if (n == 0) {
        for (int m = tid; m < lim; m += 256) { wh[m] = z; wl[m] = z; }
        return;
    }
    __shared__ float red[8];
    float mx = -3.0e38f;
    for (int m = tid; m < n; m += 256) mx = fmaxf(mx, row[m]);
#pragma unroll
    for (int o = 16; o > 0; o >>= 1) mx = fmaxf(mx, __shfl_xor_sync(0xffffffffu, mx, o));
    if ((tid & 31) == 0) red[tid >> 5] = mx;
    __syncthreads();
    float bmx = red[0];
#pragma unroll
    for (int w = 1; w < 8; ++w) bmx = fmaxf(bmx, red[w]);
    __syncthreads();
    float s = 0.f;
    for (int m = tid; m < n; m += 256) s += __expf(row[m] - bmx);
#pragma unroll
    for (int o = 16; o > 0; o >>= 1) s += __shfl_xor_sync(0xffffffffu, s, o);
    if ((tid & 31) == 0) red[tid >> 5] = s;
    __syncthreads();
    float tot = 0.f;
#pragma unroll
    for (int w = 0; w < 8; ++w) tot += red[w];
    const float inv = 1.f / tot;
    for (int m = tid; m < lim; m += 256) {
        if (m < n) {
            float wv = __expf(row[m] - bmx) * inv;
            bf h, l;
            split1(wv, h, l);
            wh[m] = h; wl[m] = l;
        } else {
            wh[m] = z; wl[m] = z;
        }
    }
}

// ---------------------------------------------------------------------------
extern "C" void kernel_launch(void* const* d_in, const int* in_sizes, int n_in,
                              void* d_out, int out_size) {
    const float* query = (const float*)d_in[0];   // [16, 2048, 512]
    const float* W_in  = (const float*)d_in[1];   // [512, 512]
    const float* W_out = (const float*)d_in[2];   // [512, 1024]
    float* out = (float*)d_out;                   // [16, 2048, 512]

    const int smem = 2 * STG_BYTES;  // 122880
    static int init = 0;
    if (!init) {
        cudaFuncSetAttribute(k_qproj,  cudaFuncAttributeMaxDynamicSharedMemorySize, smem);
        cudaFuncSetAttribute(k_scores, cudaFuncAttributeMaxDynamicSharedMemorySize, smem);
        cudaFuncSetAttribute(k_mix,    cudaFuncAttributeMaxDynamicSharedMemorySize, smem);
        cudaFuncSetAttribute(k_out,    cudaFuncAttributeMaxDynamicSharedMemorySize, smem);
        init = 1;
    }

    bf *qinh, *qinl, *winh, *winl, *wouth, *woutl;
    cudaGetSymbolAddress((void**)&qinh,  g_qinh);
    cudaGetSymbolAddress((void**)&qinl,  g_qinl);
    cudaGetSymbolAddress((void**)&winh,  g_Winh);
    cudaGetSymbolAddress((void**)&winl,  g_Winl);
    cudaGetSymbolAddress((void**)&wouth, g_Wouth);
    cudaGetSymbolAddress((void**)&woutl, g_Woutl);

    const size_t nq = (size_t)BATCH * SEQ * DIM;
    k_cvt<<<(unsigned)((nq / 4 + 255) / 256), 256>>>(query, qinh, qinl, nq);
    k_cvt<<<(DIM * DIM / 4 + 255) / 256, 256>>>(W_in, winh, winl, DIM * DIM);
    k_cvt<<<(DIM * 2 * DIM / 4 + 255) / 256, 256>>>(W_out, wouth, woutl, DIM * 2 * DIM);

    k_qproj    <<<dim3(DIM / 256, (BATCH * SEQ) / 128), 256, smem>>>();
    k_transpose<<<dim3(SEQ / 32, DIM / 32, BATCH),      256>>>();
    k_scores   <<<dim3(SEQ / 256, SEQ / 128, BATCH),    256, smem>>>();
    k_softmax  <<<dim3(SEQ, BATCH),                     256>>>();
    k_mix      <<<dim3(DIM / 256, SEQ / 128, BATCH),    256, smem>>>();
    k_out      <<<dim3(DIM / 256, (BATCH * SEQ) / 128), 256, smem>>>(out);
}

// round 11
// speedup vs baseline: 1.2473x; 1.2473x over previous
#include <cuda_runtime.h>
#include <cuda_bf16.h>
#include <cstdint>

#define BATCH 16
#define SEQ   2048
#define DIM   512
typedef __nv_bfloat16 bf;

// ---------------------------------------------------------------------------
// Persistent scratch (device globals — allocation-free per harness rules)
// ---------------------------------------------------------------------------
__device__ bf    g_qinh[(size_t)BATCH * SEQ * DIM];   // query hi
__device__ bf    g_qinl[(size_t)BATCH * SEQ * DIM];   // query lo
__device__ bf    g_Winh[DIM * DIM];
__device__ bf    g_Winl[DIM * DIM];
__device__ bf    g_Wouth[DIM * 2 * DIM];
__device__ bf    g_Woutl[DIM * 2 * DIM];
__device__ bf    g_qh  [(size_t)BATCH * SEQ * DIM];   // q hi/lo
__device__ bf    g_ql  [(size_t)BATCH * SEQ * DIM];
__device__ bf    g_qTh [(size_t)BATCH * DIM * SEQ];   // q^T hi/lo
__device__ bf    g_qTl [(size_t)BATCH * DIM * SEQ];
__device__ bf    g_Wh  [(size_t)BATCH * SEQ * SEQ];   // softmax weights hi/lo
__device__ bf    g_Wl  [(size_t)BATCH * SEQ * SEQ];
__device__ bf    g_mixh[(size_t)BATCH * SEQ * DIM];
__device__ bf    g_mixl[(size_t)BATCH * SEQ * DIM];
__device__ float g_S   [(size_t)BATCH * SEQ * SEQ];   // fp32 scores

// ---------------------------------------------------------------------------
// PTX helpers (portable: ldmatrix / mma.sync / cp.async)
// ---------------------------------------------------------------------------
__device__ __forceinline__ uint32_t smem_u32(const void* p) {
    uint32_t a;
    asm("{ .reg .u64 t; cvta.to.shared.u64 t, %1; cvt.u32.u64 %0, t; }" : "=r"(a) : "l"(p));
    return a;
}
__device__ __forceinline__ void ldsm4(uint32_t* r, uint32_t addr) {
    asm volatile("ldmatrix.sync.aligned.m8n8.x4.shared.b16 {%0,%1,%2,%3}, [%4];"
                 : "=r"(r[0]), "=r"(r[1]), "=r"(r[2]), "=r"(r[3]) : "r"(addr));
}
__device__ __forceinline__ void mma16816(float* c, const uint32_t* a, const uint32_t* b) {
    asm volatile(
        "mma.sync.aligned.m16n8k16.row.col.f32.bf16.bf16.f32 "
        "{%0,%1,%2,%3}, {%4,%5,%6,%7}, {%8,%9}, {%0,%1,%2,%3};"
        : "+f"(c[0]), "+f"(c[1]), "+f"(c[2]), "+f"(c[3])
        : "r"(a[0]), "r"(a[1]), "r"(a[2]), "r"(a[3]), "r"(b[0]), "r"(b[1]));
}
#define CP16(s, g)  asm volatile("cp.async.cg.shared.global [%0], [%1], 16;" :: "r"(s), "l"(g) : "memory")
#define CP_COMMIT() asm volatile("cp.async.commit_group;" ::: "memory")
#define CP_WAIT0()  asm volatile("cp.async.wait_group 0;" ::: "memory")

__device__ __forceinline__ void split1(float v, bf& h, bf& l) {
    h = __float2bfloat16_rn(v);
    l = __float2bfloat16_rn(v - __bfloat162float(h));
}

// ---------------------------------------------------------------------------
// GEMM: C[128x128] = A @ B^T, bf16 hi/lo inputs, 3-term split, fp32 accum.
// All operands K-major bf16. K = nk*32. CONCAT: chunks>=16 read A1 (lda 512).
// EPI: 0 -> fp32 C, 1 -> bf16 hi/lo pair (Ch, Cl).
// 256 threads = 8 warps (4m x 2n), warp tile 32x64, mma m16n8k16.
// 2-stage cp.async pipeline, one __syncthreads per chunk, 2 CTA/SM.
// MMA issue order: per 4-col B group, all hh then all hl then all lh ->
// same-acc dependence distance 8 (covers HMMA RAW latency).
// ---------------------------------------------------------------------------
#define LDS 40  // bf16 per smem row (80B; 16B-aligned segments, conflict-free ldmatrix)
#define STG_BYTES (4 * 128 * LDS * 2)  // one stage: Ah,Al,Bh,Bl

template<int CONCAT, int EPI>
__device__ __forceinline__ void gemm_bf(
    const bf* __restrict__ Ah, const bf* __restrict__ Al,
    const bf* __restrict__ A1h, const bf* __restrict__ A1l, long lda,
    const bf* __restrict__ Bh, const bf* __restrict__ Bl, long ldb,
    int nk,
    float* __restrict__ C, bf* __restrict__ Ch, bf* __restrict__ Cl, long ldc,
    int m0, int n0)
{
    extern __shared__ bf sm[];
    const uint32_t uS = smem_u32(sm);

    const int tid = threadIdx.x;
    const int wid = tid >> 5, lane = tid & 31;
    const int wm = wid >> 1, wn = wid & 1;
    const int r = tid >> 1, h16 = (tid & 1) << 4;   // loader: row, 16-elem half

    const uint32_t rowoff = ((uint32_t)r * LDS + h16) * 2;

    auto issue = [&](int kc, int st) {
        const bf* a_h;
        const bf* a_l;
        if (CONCAT && kc >= 16) {
            a_h = A1h + (size_t)(m0 + r) * 512 + (size_t)(kc - 16) * 32 + h16;
            a_l = A1l + (size_t)(m0 + r) * 512 + (size_t)(kc - 16) * 32 + h16;
        } else {
            a_h = Ah + (size_t)(m0 + r) * lda + (size_t)kc * 32 + h16;
            a_l = Al + (size_t)(m0 + r) * lda + (size_t)kc * 32 + h16;
        }
        const bf* b_h = Bh + (size_t)(n0 + r) * ldb + (size_t)kc * 32 + h16;
        const bf* b_l = Bl + (size_t)(n0 + r) * ldb + (size_t)kc * 32 + h16;
        const uint32_t base = uS + (uint32_t)st * STG_BYTES + rowoff;
        CP16(base + 0 * 128 * LDS * 2,      a_h);
        CP16(base + 0 * 128 * LDS * 2 + 16, a_h + 8);
        CP16(base + 1 * 128 * LDS * 2,      a_l);
        CP16(base + 1 * 128 * LDS * 2 + 16, a_l + 8);
        CP16(base + 2 * 128 * LDS * 2,      b_h);
        CP16(base + 2 * 128 * LDS * 2 + 16, b_h + 8);
        CP16(base + 3 * 128 * LDS * 2,      b_l);
        CP16(base + 3 * 128 * LDS * 2 + 16, b_l + 8);
    };

    float acc[2][8][4] = {};

    issue(0, 0);
    CP_COMMIT();

    for (int kc = 0; kc < nk; ++kc) {
        const int st = kc & 1;
        CP_WAIT0();
        __syncthreads();
        if (kc + 1 < nk) { issue(kc + 1, st ^ 1); CP_COMMIT(); }

        const uint32_t sA  = uS + (uint32_t)st * STG_BYTES;
        const uint32_t sAl_ = sA + 128 * LDS * 2;
        const uint32_t sB  = sA + 2 * 128 * LDS * 2;
        const uint32_t sBl_ = sA + 3 * 128 * LDS * 2;

#pragma unroll
        for (int kk = 0; kk < 2; ++kk) {
            const uint32_t aoff =
                ((uint32_t)(wm * 32 + (lane & 15)) * LDS + kk * 16 + ((lane & 16) ? 8 : 0)) * 2;
            uint32_t ah[2][4], al[2][4];
            ldsm4(ah[0], sA + aoff);
            ldsm4(ah[1], sA + aoff + 16 * LDS * 2);
            ldsm4(al[0], sAl_ + aoff);
            ldsm4(al[1], sAl_ + aoff + 16 * LDS * 2);

            const uint32_t boff =
                ((uint32_t)(wn * 64 + (lane & 7) + ((lane & 16) ? 8 : 0)) * LDS
                 + kk * 16 + ((lane & 8) ? 8 : 0)) * 2;

#pragma unroll
            for (int jh = 0; jh < 2; ++jh) {
                // load B frags for this 32-col group: j = jh*4 .. jh*4+3
                uint32_t bh[4][2], bl[4][2];
#pragma unroll
                for (int jj = 0; jj < 2; ++jj) {
                    uint32_t tb[4], tl[4];
                    const uint32_t bo = boff + (jh * 2 + jj) * 16 * LDS * 2;
                    ldsm4(tb, sB + bo);
                    ldsm4(tl, sBl_ + bo);
                    bh[2 * jj][0] = tb[0]; bh[2 * jj][1] = tb[1];
                    bh[2 * jj + 1][0] = tb[2]; bh[2 * jj + 1][1] = tb[3];
                    bl[2 * jj][0] = tl[0]; bl[2 * jj][1] = tl[1];
                    bl[2 * jj + 1][0] = tl[2]; bl[2 * jj + 1][1] = tl[3];
                }
                // pass 1: hi*hi (8 independent MMAs)
#pragma unroll
                for (int im = 0; im < 2; ++im)
#pragma unroll
                    for (int j = 0; j < 4; ++j)
                        mma16816(acc[im][jh * 4 + j], ah[im], bh[j]);
                // pass 2: hi*lo
#pragma unroll
                for (int im = 0; im < 2; ++im)
#pragma unroll
                    for (int j = 0; j < 4; ++j)
                        mma16816(acc[im][jh * 4 + j], ah[im], bl[j]);
                // pass 3: lo*hi
#pragma unroll
                for (int im = 0; im < 2; ++im)
#pragma unroll
                    for (int j = 0; j < 4; ++j)
                        mma16816(acc[im][jh * 4 + j], al[im], bh[j]);
            }
        }
    }

    // epilogue
    const int g = lane >> 2, tg = lane & 3;
#pragma unroll
    for (int im = 0; im < 2; ++im) {
        const size_t row = (size_t)(m0 + wm * 32 + im * 16 + g);
#pragma unroll
        for (int j = 0; j < 8; ++j) {
            const size_t col = (size_t)(n0 + wn * 64 + j * 8 + tg * 2);
            if (EPI == 0) {
                *(float2*)(C + row * ldc + col)       = make_float2(acc[im][j][0], acc[im][j][1]);
                *(float2*)(C + (row + 8) * ldc + col) = make_float2(acc[im][j][2], acc[im][j][3]);
            } else {
                bf h0, l0, h1, l1;
#pragma unroll
                for (int p = 0; p < 2; ++p) {
                    const size_t rr = (row + p * 8) * ldc + col;
                    split1(acc[im][j][2 * p],     h0, l0);
                    split1(acc[im][j][2 * p + 1], h1, l1);
                    *(uint32_t*)(Ch + rr) = ((uint32_t)__bfloat16_as_ushort(h1) << 16) | __bfloat16_as_ushort(h0);
                    *(uint32_t*)(Cl + rr) = ((uint32_t)__bfloat16_as_ushort(l1) << 16) | __bfloat16_as_ushort(l0);
                }
            }
        }
    }
}

// ---------------------------------------------------------------------------
// GEMM kernels
// ---------------------------------------------------------------------------
__global__ void __launch_bounds__(256, 2) k_qproj() {
    gemm_bf<0, 1>(g_qinh, g_qinl, nullptr, nullptr, DIM,
                  g_Winh, g_Winl, DIM, 16,
                  nullptr, g_qh, g_ql, DIM, blockIdx.y * 128, blockIdx.x * 128);
}
__global__ void __launch_bounds__(256, 2) k_scores() {
    if (blockIdx.x > blockIdx.y) return;   // fully masked causal tile
    const size_t qo = (size_t)blockIdx.z * SEQ * DIM;
    gemm_bf<0, 0>(g_qh + qo, g_ql + qo, nullptr, nullptr, DIM,
                  g_qh + qo, g_ql + qo, DIM, 16,
                  g_S + (size_t)blockIdx.z * SEQ * SEQ, nullptr, nullptr, SEQ,
                  blockIdx.y * 128, blockIdx.x * 128);
}
__global__ void __launch_bounds__(256, 2) k_mix() {
    const int b = blockIdx.z, m0 = blockIdx.y * 128, n0 = blockIdx.x * 128;
    const size_t wo = (size_t)b * SEQ * SEQ, qo = (size_t)b * DIM * SEQ;
    const size_t mo = (size_t)b * SEQ * DIM;
    gemm_bf<0, 1>(g_Wh + wo, g_Wl + wo, nullptr, nullptr, SEQ,
                  g_qTh + qo, g_qTl + qo, SEQ, m0 / 32 + 4,
                  nullptr, g_mixh + mo, g_mixl + mo, DIM, m0, n0);
}
__global__ void __launch_bounds__(256, 2) k_out(float* __restrict__ out) {
    gemm_bf<1, 0>(g_mixh, g_mixl, g_qh, g_ql, DIM,
                  g_Wouth, g_Woutl, 2 * DIM, 32,
                  out, nullptr, nullptr, DIM, blockIdx.y * 128, blockIdx.x * 128);
}

// ---------------------------------------------------------------------------
// fp32 -> bf16 hi/lo split (pre-convert inputs)
// ---------------------------------------------------------------------------
__global__ void __launch_bounds__(256) k_cvt(const float* __restrict__ src,
                                             bf* __restrict__ dh, bf* __restrict__ dl,
                                             size_t n) {
    size_t i = ((size_t)blockIdx.x * 256 + threadIdx.x) * 4;
    if (i >= n) return;
    float4 v = *(const float4*)(src + i);
    bf h0, l0, h1, l1, h2, l2, h3, l3;
    split1(v.x, h0, l0); split1(v.y, h1, l1);
    split1(v.z, h2, l2); split1(v.w, h3, l3);
    *(uint2*)(dh + i) = make_uint2(
        ((uint32_t)__bfloat16_as_ushort(h1) << 16) | __bfloat16_as_ushort(h0),
        ((uint32_t)__bfloat16_as_ushort(h3) << 16) | __bfloat16_as_ushort(h2));
    *(uint2*)(dl + i) = make_uint2(
        ((uint32_t)__bfloat16_as_ushort(l1) << 16) | __bfloat16_as_ushort(l0),
        ((uint32_t)__bfloat16_as_ushort(l3) << 16) | __bfloat16_as_ushort(l2));
}

// ---------------------------------------------------------------------------
// Transpose bf16 hi/lo: qT[b][d][n] = q[b][n][d]
// ---------------------------------------------------------------------------
__global__ void __launch_bounds__(256) k_transpose() {
    __shared__ bf th[32][33];
    __shared__ bf tl[32][33];
    const int b = blockIdx.z, n0 = blockIdx.x * 32, d0 = blockIdx.y * 32;
    const int tx = threadIdx.x & 31, ty = threadIdx.x >> 5;
    const size_t so = (size_t)b * SEQ * DIM, to = (size_t)b * DIM * SEQ;
#pragma unroll
    for (int j = 0; j < 4; ++j) {
        const size_t idx = so + (size_t)(n0 + ty + 8 * j) * DIM + d0 + tx;
        th[ty + 8 * j][tx] = g_qh[idx];
        tl[ty + 8 * j][tx] = g_ql[idx];
    }
    __syncthreads();
#pragma unroll
    for (int j = 0; j < 4; ++j) {
        const size_t idx = to + (size_t)(d0 + ty + 8 * j) * SEQ + n0 + tx;
        g_qTh[idx] = th[tx][ty + 8 * j];
        g_qTl[idx] = tl[tx][ty + 8 * j];
    }
}

// ---------------------------------------------------------------------------
// Softmax: row n over keys m < n (strict causal); emits bf16 hi/lo weights.
// Row cached in registers: ONE global read, exp computed once.
// Writes only up to the 128-aligned limit that k_mix reads.
// ---------------------------------------------------------------------------
__global__ void __launch_bounds__(256) k_softmax() {
    const int n = blockIdx.x, b = blockIdx.y;
    const size_t ro = ((size_t)b * SEQ + n) * SEQ;
    const float* row = g_S + ro;
    bf* wh = g_Wh + ro;
    bf* wl = g_Wl + ro;
    const int tid = threadIdx.x;
    const int lim = (n / 128) * 128 + 128;   // k_mix never reads beyond this
    const bf z = __float2bfloat16_rn(0.f);
    if (n == 0) {
        for (int m = tid; m < lim; m += 256) { wh[m] = z; wl[m] = z; }
        return;
    }
    __shared__ float red[8];
    float f[8];
    // single read of the active row prefix into registers
#pragma unroll
    for (int i = 0; i < 8; ++i) {
        const int m = tid + i * 256;
        f[i] = (m < n) ? row[m] : -3.0e38f;
    }
    float mx = -3.0e38f;
#pragma unroll
    for (int i = 0; i < 8; ++i) mx = fmaxf(mx, f[i]);
#pragma unroll
    for (int o = 16; o > 0; o >>= 1) mx = fmaxf(mx, __shfl_xor_sync(0xffffffffu, mx, o));
    if ((tid & 31) == 0) red[tid >> 5] = mx;
    __syncthreads();
    float bmx = red[0];
#pragma unroll
    for (int w = 1; w < 8; ++w) bmx = fmaxf(bmx, red[w]);
    __syncthreads();
    float s = 0.f;
#pragma unroll
    for (int i = 0; i < 8; ++i) {
        const int m = tid + i * 256;
        f[i] = (m < n) ? __expf(f[i] - bmx) : 0.f;
        s += f[i];
    }
#pragma unroll
    for (int o = 16; o > 0; o >>= 1) s += __shfl_xor_sync(0xffffffffu, s, o);
    if ((tid & 31) == 0) red[tid >> 5] = s;
    __syncthreads();
    float tot = 0.f;
#pragma unroll
    for (int w = 0; w < 8; ++w) tot += red[w];
    const float inv = 1.f / tot;
#pragma unroll
    for (int i = 0; i < 8; ++i) {
        const int m = tid + i * 256;
        if (m < lim) {
            const float wv = f[i] * inv;   // 0 for m >= n
            bf h, l;
            split1(wv, h, l);
            wh[m] = h; wl[m] = l;
        }
    }
}

// ---------------------------------------------------------------------------
extern "C" void kernel_launch(void* const* d_in, const int* in_sizes, int n_in,
                              void* d_out, int out_size) {
    const float* query = (const float*)d_in[0];   // [16, 2048, 512]
    const float* W_in  = (const float*)d_in[1];   // [512, 512]
    const float* W_out = (const float*)d_in[2];   // [512, 1024]
    float* out = (float*)d_out;                   // [16, 2048, 512]

    const int smem = 2 * STG_BYTES;  // 81920
    static int init = 0;
    if (!init) {
        cudaFuncSetAttribute(k_qproj,  cudaFuncAttributeMaxDynamicSharedMemorySize, smem);
        cudaFuncSetAttribute(k_scores, cudaFuncAttributeMaxDynamicSharedMemorySize, smem);
        cudaFuncSetAttribute(k_mix,    cudaFuncAttributeMaxDynamicSharedMemorySize, smem);
        cudaFuncSetAttribute(k_out,    cudaFuncAttributeMaxDynamicSharedMemorySize, smem);
        init = 1;
    }

    bf *qinh, *qinl, *winh, *winl, *wouth, *woutl;
    cudaGetSymbolAddress((void**)&qinh,  g_qinh);
    cudaGetSymbolAddress((void**)&qinl,  g_qinl);
    cudaGetSymbolAddress((void**)&winh,  g_Winh);
    cudaGetSymbolAddress((void**)&winl,  g_Winl);
    cudaGetSymbolAddress((void**)&wouth, g_Wouth);
    cudaGetSymbolAddress((void**)&woutl, g_Woutl);

    const size_t nq = (size_t)BATCH * SEQ * DIM;
    k_cvt<<<(unsigned)((nq / 4 + 255) / 256), 256>>>(query, qinh, qinl, nq);
    k_cvt<<<(DIM * DIM / 4 + 255) / 256, 256>>>(W_in, winh, winl, DIM * DIM);
    k_cvt<<<(DIM * 2 * DIM / 4 + 255) / 256, 256>>>(W_out, wouth, woutl, DIM * 2 * DIM);

    k_qproj    <<<dim3(DIM / 128, (BATCH * SEQ) / 128), 256, smem>>>();
    k_transpose<<<dim3(SEQ / 32, DIM / 32, BATCH),      256>>>();
    k_scores   <<<dim3(SEQ / 128, SEQ / 128, BATCH),    256, smem>>>();
    k_softmax  <<<dim3(SEQ, BATCH),                     256>>>();
    k_mix      <<<dim3(DIM / 128, SEQ / 128, BATCH),    256, smem>>>();
    k_out      <<<dim3(DIM / 128, (BATCH * SEQ) / 128), 256, smem>>>(out);
}